// round 14
// baseline (speedup 1.0000x reference)
#include <cuda_runtime.h>
#include <cuda_fp16.h>
#include <cstdint>
#include <cstddef>

#define B_  8
#define N_  1024
#define R_  16384
#define MR_ (B_*R_)
#define MN_ (B_*N_)
#define KSL 16

typedef __half h16;

// ------------------------- scratch (device globals) -------------------------
__device__ h16 g_RsT_h[(size_t)R_*N_];
__device__ h16 g_RrT_h[(size_t)R_*N_];
__device__ h16 g_Rr_h [(size_t)N_*R_];
__device__ h16 g_oT_h [(size_t)256*N_];
__device__ h16 g_nd_h [(size_t)MR_*64];
__device__ h16 g_h1_h [(size_t)MR_*512];
__device__ h16 g_h2_h [(size_t)MR_*512];
__device__ h16 g_eT_h [(size_t)512*R_];
__device__ float g_part[(size_t)KSL*N_*512];
__device__ h16 g_up_h [(size_t)MN_*128];
__device__ h16 g_hn_h [(size_t)MN_*512];
__device__ h16 g_w1_h[512*64],  g_w1_l[512*64];
__device__ h16 g_w2_h[512*512];
__device__ h16 g_w3_h[64*512],  g_w3_l[64*512];
__device__ h16 g_w4_h[64*64],   g_w4_l[64*64];
__device__ h16 g_v1_h[512*128], g_v1_l[512*128];
__device__ h16 g_v2_h[32*512],  g_v2_l[32*512];

// ------------------------------- helpers ------------------------------------
__device__ __forceinline__ uint32_t smem_u32(const void* p){
    uint32_t a; asm("{ .reg .u64 t; cvta.to.shared.u64 t, %1; cvt.u32.u64 %0, t; }":"=r"(a):"l"(p)); return a;
}
__device__ __forceinline__ uint32_t swz(uint32_t off){ return off ^ ((off>>3)&0x70); }

__device__ __forceinline__ void cp16(uint32_t dst, const void* src){
    asm volatile("cp.async.cg.shared.global [%0], [%1], 16;" :: "r"(dst), "l"(src) : "memory");
}
__device__ __forceinline__ void cp_commit(){ asm volatile("cp.async.commit_group;" ::: "memory"); }

__device__ __forceinline__ void ldm_x4(uint32_t* r,uint32_t a){
    asm volatile("ldmatrix.sync.aligned.m8n8.x4.shared.b16 {%0,%1,%2,%3},[%4];"
        :"=r"(r[0]),"=r"(r[1]),"=r"(r[2]),"=r"(r[3]):"r"(a));
}
__device__ __forceinline__ void ldm_x2(uint32_t* r,uint32_t a){
    asm volatile("ldmatrix.sync.aligned.m8n8.x2.shared.b16 {%0,%1},[%2];"
        :"=r"(r[0]),"=r"(r[1]):"r"(a));
}
__device__ __forceinline__ void mma_f16(float* d,const uint32_t* a,const uint32_t* b){
    asm volatile("mma.sync.aligned.m16n8k16.row.col.f32.f16.f16.f32 "
        "{%0,%1,%2,%3},{%4,%5,%6,%7},{%8,%9},{%0,%1,%2,%3};"
        : "+f"(d[0]),"+f"(d[1]),"+f"(d[2]),"+f"(d[3])
        : "r"(a[0]),"r"(a[1]),"r"(a[2]),"r"(a[3]),"r"(b[0]),"r"(b[1]));
}

// --------------------------- HMMA fp16 GEMM ---------------------------------
// D[M,N] = act(A[M,K] @ B[N,K]^T + bias).  A = fp16 hi plane.
// PASSES=2: B = hi+lo planes (2 MMA passes). PASSES=1: B = hi only.
// 128-row M tiles, NT-col N tiles, K chunks of 64, cp.async double buffer.
// Buffer p at p*BUF: A @0 (16KB), B hi @16384 [, B lo @16384+BPL].
// MODE: 0 fp16 out (ldc); 1 fp32 out (ldc); 2 transposed edgeT out;
//       3 gather node out (ldc = col base 0/32).
template<int NT,int MODE,bool RELU,int PASSES>
__global__ __launch_bounds__(256)
void hm_gemm(const h16* __restrict__ Ah,int lda,
             const h16* __restrict__ Bh,const h16* __restrict__ Bl,int ldb,
             const float* __restrict__ bias,void* C0v,void* C1v,int ldc,
             size_t cZ,int stages,int kZ)
{
    extern __shared__ char smem[];
    const uint32_t sb = smem_u32(smem);
    const int tid=threadIdx.x, w=tid>>5, lane=tid&31;
    const int z=blockIdx.z, m0=blockIdx.y*128, n0=blockIdx.x*NT;
    const int kbase=z*kZ;
    constexpr int BPL = NT*128;                 // bytes per B plane
    constexpr uint32_t BUF = 16384u + (uint32_t)PASSES*BPL;
    constexpr int WARPS_M = (NT==128)?2:4;
    constexpr int WARPS_N = 8/WARPS_M;
    constexpr int WM = 128/WARPS_M;
    constexpr int WN = NT/WARPS_N;
    constexpr int MT = WM/16, NF = WN/8;
    const int wr = w % WARPS_M, wc = w / WARPS_M;

    float* Cf=nullptr; h16* Ch=nullptr; h16* Cl=nullptr;
    if(MODE==1) Cf=(float*)C0v + (size_t)z*cZ;
    else { Ch=(h16*)C0v; Cl=(h16*)C1v; }

    float acc[MT][NF][4];
#pragma unroll
    for(int i=0;i<MT;i++)
#pragma unroll
        for(int j=0;j<NF;j++)
#pragma unroll
            for(int q=0;q<4;q++) acc[i][j][q]=0.f;

    auto load_stage = [&](int s){
        const int kk = kbase + s*64;
        const uint32_t base = sb + (uint32_t)(s&1)*BUF;
#pragma unroll
        for(int it=0;it<4;it++){
            int idx=tid+it*256, row=idx>>3, c=idx&7;
            cp16(base+swz((uint32_t)(row*128+c*16)),
                 Ah+(size_t)(m0+row)*lda+kk+c*8);
        }
#pragma unroll
        for(int pl=0;pl<PASSES;pl++){
            const h16* src = pl?Bl:Bh;
            const uint32_t dofs = base + 16384u + (uint32_t)pl*BPL;
#pragma unroll
            for(int it=0;it<NT/32;it++){
                int idx=tid+it*256, row=idx>>3, c=idx&7;
                cp16(dofs+swz((uint32_t)(row*128+c*16)),
                     src+(size_t)(n0+row)*ldb+kk+c*8);
            }
        }
        cp_commit();
    };

    load_stage(0);

    for(int s=0;s<stages;s++){
        if(s+1<stages){
            load_stage(s+1);
            asm volatile("cp.async.wait_group 1;" ::: "memory");
        } else {
            asm volatile("cp.async.wait_group 0;" ::: "memory");
        }
        __syncthreads();

        const uint32_t base = sb + (uint32_t)(s&1)*BUF;
        const uint32_t bbase = base + 16384u;
#pragma unroll
        for(int k16=0;k16<4;k16++){
            uint32_t bh[NF][2], bl[NF][2];
#pragma unroll
            for(int nf=0;nf<NF;nf++){
                int row = wc*WN + nf*8 + (lane&7);
                int colb = k16*32 + ((lane>>3)&1)*16;
                uint32_t off = swz((uint32_t)(row*128+colb));
                ldm_x2(bh[nf], bbase + off);
                if(PASSES==2) ldm_x2(bl[nf], bbase + BPL + off);
            }
            uint32_t ar[MT][4];
#pragma unroll
            for(int mt=0;mt<MT;mt++){
                int row = wr*WM + mt*16 + (lane&15);
                int colb = k16*32 + (lane>>4)*16;
                ldm_x4(ar[mt], base + swz((uint32_t)(row*128+colb)));
            }
#pragma unroll
            for(int mt=0;mt<MT;mt++)
#pragma unroll
                for(int nf=0;nf<NF;nf++){
                    mma_f16(acc[mt][nf], ar[mt], bh[nf]);
                    if(PASSES==2) mma_f16(acc[mt][nf], ar[mt], bl[nf]);
                }
        }
        __syncthreads();
    }

    // ------------------------------- epilogue -------------------------------
    if(MODE==2){
        float* fbuf = reinterpret_cast<float*>(smem);
#pragma unroll
        for(int mt=0;mt<MT;mt++)
#pragma unroll
            for(int nf=0;nf<NF;nf++){
                int ln = wc*WN + nf*8 + 2*(lane&3);
                float b0=0.f,b1=0.f;
                if(bias){ b0=bias[n0+ln]; b1=bias[n0+ln+1]; }
#pragma unroll
                for(int rr=0;rr<2;rr++){
                    int lm = wr*WM + mt*16 + (lane>>2) + rr*8;
                    float v0=acc[mt][nf][rr*2+0]+b0;
                    float v1=acc[mt][nf][rr*2+1]+b1;
                    if(RELU){ v0=fmaxf(v0,0.f); v1=fmaxf(v1,0.f); }
                    fbuf[lm*(NT+1)+ln]=v0;
                    fbuf[lm*(NT+1)+ln+1]=v1;
                }
            }
        __syncthreads();
        const int bb = m0>>14, r0g = m0&(R_-1);
        for(int idx=tid; idx<NT*128; idx+=256){
            int nn=idx>>7, mm=idx&127;
            float v=fbuf[mm*(NT+1)+nn];
            size_t o=((size_t)bb*64+(n0+nn))*(size_t)R_ + r0g+mm;
            Ch[o]=__float2half_rn(v);
            if(Cl) Cl[o]=__float2half_rn(v-__half2float(__float2half_rn(v)));
        }
        return;
    }

#pragma unroll
    for(int mt=0;mt<MT;mt++)
#pragma unroll
        for(int nf=0;nf<NF;nf++){
            int c0 = n0 + wc*WN + nf*8 + 2*(lane&3);
            float b0=0.f,b1=0.f;
            if(bias){ b0=bias[c0]; b1=bias[c0+1]; }
#pragma unroll
            for(int rr=0;rr<2;rr++){
                int gm = m0 + wr*WM + mt*16 + (lane>>2) + rr*8;
                float v0=acc[mt][nf][rr*2+0]+b0;
                float v1=acc[mt][nf][rr*2+1]+b1;
                if(RELU){ v0=fmaxf(v0,0.f); v1=fmaxf(v1,0.f); }
                if(MODE==1){
                    *reinterpret_cast<float2*>(Cf+(size_t)gm*ldc+c0)=make_float2(v0,v1);
                } else {
                    size_t o;
                    if(MODE==0) o=(size_t)gm*ldc+c0;
                    else        o=((size_t)(c0>>5)*R_+gm)*64 + ldc + (c0&31);
                    *reinterpret_cast<__half2*>(Ch+o)=__floats2half2_rn(v0,v1);
                }
            }
        }
}

// ------------------------------- prep kernels -------------------------------
// transpose+split: fp32 [P,Q](ldin) -> fp16 hi [Q,ldout] (+lo if ol) ;
// optional straight fp16 copy (same [P,ldin] layout) via cpy.
__global__ void tsplit(const float* __restrict__ in,h16* __restrict__ oh,h16* __restrict__ ol,
                       h16* __restrict__ cpy,
                       int P,int ldin,int ldout,size_t inB,size_t outB)
{
    __shared__ float t[32][33];
    in+=(size_t)blockIdx.z*inB; oh+=(size_t)blockIdx.z*outB;
    if(ol) ol+=(size_t)blockIdx.z*outB;
    int p0=blockIdx.x*32, q0=blockIdx.y*32, tx=threadIdx.x, ty=threadIdx.y;
#pragma unroll
    for(int i=0;i<4;i++){
        int p=p0+ty+i*8; float v=0.f;
        if(p<P){
            v=in[(size_t)p*ldin+q0+tx];
            if(cpy) cpy[(size_t)p*ldin+q0+tx]=__float2half_rn(v);
        }
        t[ty+i*8][tx]=v;
    }
    __syncthreads();
#pragma unroll
    for(int i=0;i<4;i++){
        int q=q0+ty+i*8, pp=p0+tx;
        float v=t[tx][ty+i*8];
        h16 hi=__float2half_rn(v);
        oh[(size_t)q*ldout+pp]=hi;
        if(ol) ol[(size_t)q*ldout+pp]=__float2half_rn(v-__half2float(hi));
    }
}
// reduce split-K partials + concat -> up hi plane [MN,128] (cols 96..127 = 0)
__global__ void reduce_concat(const float* __restrict__ obj,const float* __restrict__ part,
                              h16* __restrict__ uh)
{
    int i=blockIdx.x*256+threadIdx.x; if(i>=MN_*128) return;
    int col=i&127, bn=i>>7;
    float v=0.f;
    if(col<32) v=obj[(size_t)bn*32+col];
    else if(col<96){
        int e=col-32, b=bn>>10, n=bn&1023;
        size_t base=(size_t)n*512+b*64+e;
#pragma unroll
        for(int ks=0;ks<KSL;ks++) v+=part[(size_t)ks*N_*512+base];
    }
    uh[i]=__float2half_rn(v);
}

// ---------------------------------- host ------------------------------------
static inline int smB(int nt,int passes){ return 2*(16384 + passes*nt*128); }

extern "C" void kernel_launch(void* const* d_in,const int* in_sizes,int n_in,
                              void* d_out,int out_size)
{
    const float* obj=(const float*)d_in[0];
    const float* Rs =(const float*)d_in[1];
    const float* Rr =(const float*)d_in[2];
    const float* rw1=(const float*)d_in[3];  const float* rb1=(const float*)d_in[4];
    const float* rw2=(const float*)d_in[5];  const float* rb2=(const float*)d_in[6];
    const float* rw3=(const float*)d_in[7];  const float* rb3=(const float*)d_in[8];
    const float* rw4=(const float*)d_in[9];  const float* rb4=(const float*)d_in[10];
    const float* ow1=(const float*)d_in[11]; const float* ob1=(const float*)d_in[12];
    const float* ow2=(const float*)d_in[13]; const float* ob2=(const float*)d_in[14];
    float* out=(float*)d_out;

    h16 *RsTh,*RrTh,*Rrh,*oTh,*ndh,*h1h,*h2h,*eTh,*uph,*hnh;
    h16 *w1h,*w1l,*w2h,*w3h,*w3l,*w4h,*w4l,*v1h,*v1l,*v2h,*v2l;
    float* part;
    cudaGetSymbolAddress((void**)&RsTh,g_RsT_h);
    cudaGetSymbolAddress((void**)&RrTh,g_RrT_h);
    cudaGetSymbolAddress((void**)&Rrh,g_Rr_h);
    cudaGetSymbolAddress((void**)&oTh,g_oT_h);
    cudaGetSymbolAddress((void**)&ndh,g_nd_h);
    cudaGetSymbolAddress((void**)&h1h,g_h1_h);
    cudaGetSymbolAddress((void**)&h2h,g_h2_h);
    cudaGetSymbolAddress((void**)&eTh,g_eT_h);
    cudaGetSymbolAddress((void**)&part,g_part);
    cudaGetSymbolAddress((void**)&uph,g_up_h);
    cudaGetSymbolAddress((void**)&hnh,g_hn_h);
    cudaGetSymbolAddress((void**)&w1h,g_w1_h);   cudaGetSymbolAddress((void**)&w1l,g_w1_l);
    cudaGetSymbolAddress((void**)&w2h,g_w2_h);
    cudaGetSymbolAddress((void**)&w3h,g_w3_h);   cudaGetSymbolAddress((void**)&w3l,g_w3_l);
    cudaGetSymbolAddress((void**)&w4h,g_w4_h);   cudaGetSymbolAddress((void**)&w4l,g_w4_l);
    cudaGetSymbolAddress((void**)&v1h,g_v1_h);   cudaGetSymbolAddress((void**)&v1l,g_v1_l);
    cudaGetSymbolAddress((void**)&v2h,g_v2_h);   cudaGetSymbolAddress((void**)&v2l,g_v2_l);

    cudaFuncSetAttribute(hm_gemm<128,3,false,1>,cudaFuncAttributeMaxDynamicSharedMemorySize,smB(128,1));
    cudaFuncSetAttribute(hm_gemm<128,0,true ,2>,cudaFuncAttributeMaxDynamicSharedMemorySize,smB(128,2));
    cudaFuncSetAttribute(hm_gemm<128,0,true ,1>,cudaFuncAttributeMaxDynamicSharedMemorySize,smB(128,1));
    cudaFuncSetAttribute(hm_gemm< 64,0,true ,2>,cudaFuncAttributeMaxDynamicSharedMemorySize,smB(64,2));
    cudaFuncSetAttribute(hm_gemm< 64,2,true ,2>,cudaFuncAttributeMaxDynamicSharedMemorySize,smB(64,2));
    cudaFuncSetAttribute(hm_gemm<128,1,false,1>,cudaFuncAttributeMaxDynamicSharedMemorySize,smB(128,1));
    cudaFuncSetAttribute(hm_gemm< 32,1,false,2>,cudaFuncAttributeMaxDynamicSharedMemorySize,smB(32,2));

    dim3 tb(32,8);
    // prep: transposes + splits (lo planes only for weight B operands of 2-pass layers)
    tsplit<<<dim3(32,512,1),tb>>>(Rs, RsTh,nullptr,nullptr, 1024,R_,1024, 0,0);
    tsplit<<<dim3(32,512,1),tb>>>(Rr, RrTh,nullptr,Rrh, 1024,R_,1024, 0,0);   // also straight fp16 copy
    tsplit<<<dim3(32,1,8),tb>>>(obj, oTh,nullptr,nullptr, 1024,32,1024, (size_t)N_*32,(size_t)32*N_);
    tsplit<<<dim3(2,16,1),tb>>>(rw1, w1h,w1l,nullptr, 64,512,64, 0,0);
    tsplit<<<dim3(16,16,1),tb>>>(rw2, w2h,nullptr,nullptr, 512,512,512, 0,0);
    tsplit<<<dim3(16,2,1),tb>>>(rw3, w3h,w3l,nullptr, 512,64,512, 0,0);
    tsplit<<<dim3(2,2,1),tb>>>(rw4, w4h,w4l,nullptr, 64,64,64, 0,0);
    tsplit<<<dim3(4,16,1),tb>>>(ow1, v1h,v1l,nullptr, 96,512,128, 0,0);
    tsplit<<<dim3(16,1,1),tb>>>(ow2, v2h,v2l,nullptr, 512,32,512, 0,0);

    // gather: node[b*R+r, 0:32]=src(Rs), [32:64]=dst(Rr)   (1-pass)
    hm_gemm<128,3,false,1><<<dim3(2,128,1),256,smB(128,1)>>>(RsTh,1024, oTh,nullptr,1024, nullptr, ndh,nullptr, 0, 0, 16,0);
    hm_gemm<128,3,false,1><<<dim3(2,128,1),256,smB(128,1)>>>(RrTh,1024, oTh,nullptr,1024, nullptr, ndh,nullptr, 32,0, 16,0);
    // edge MLP (L2 is 1-pass; L1/L3/L4 2-pass)
    hm_gemm<128,0,true ,2><<<dim3(4,1024,1),256,smB(128,2)>>>(ndh,64,  w1h,w1l,64,  rb1, h1h,nullptr, 512,0, 1,0);
    hm_gemm<128,0,true ,1><<<dim3(4,1024,1),256,smB(128,1)>>>(h1h,512, w2h,nullptr,512, rb2, h2h,nullptr, 512,0, 8,0);
    hm_gemm< 64,0,true ,2><<<dim3(1,1024,1),256,smB(64,2)>>>(h2h,512, w3h,w3l,512, rb3, ndh,nullptr, 64,0, 8,0);
    hm_gemm< 64,2,true ,2><<<dim3(1,1024,1),256,smB(64,2)>>>(ndh,64,  w4h,w4l,64,  rb4, eTh,nullptr, 0,0, 1,0);
    // scatter-aggregate (1-pass, split-K=16, fp32 partials), then reduce+concat
    hm_gemm<128,1,false,1><<<dim3(4,8,KSL),256,smB(128,1)>>>(Rrh,R_, eTh,nullptr,R_, nullptr, part,nullptr, 512,(size_t)N_*512, 16,1024);
    reduce_concat<<<(MN_*128+255)/256,256>>>(obj, part, uph);
    // node MLP (2-pass)
    hm_gemm<128,0,true ,2><<<dim3(4,64,1),256,smB(128,2)>>>(uph,128, v1h,v1l,128, ob1, hnh,nullptr, 512,0, 2,0);
    hm_gemm< 32,1,false,2><<<dim3(1,64,1),256,smB(32,2)>>>(hnh,512, v2h,v2l,512, ob2, out,nullptr, 32,0, 8,0);
}

// round 15
// speedup vs baseline: 1.6513x; 1.6513x over previous
#include <cuda_runtime.h>
#include <cuda_fp16.h>
#include <cstdint>
#include <cstddef>

#define B_  8
#define N_  1024
#define R_  16384
#define MR_ (B_*R_)
#define MN_ (B_*N_)
#define KSL 16

typedef __half h16;

// ------------------------- scratch (device globals) -------------------------
__device__ h16 g_RsT_h[(size_t)R_*N_];
__device__ h16 g_RrT_h[(size_t)R_*N_];
__device__ h16 g_Rr_h [(size_t)N_*R_];
__device__ h16 g_oT_h [(size_t)256*N_];
__device__ h16 g_nd_h [(size_t)MR_*64];
__device__ h16 g_h1_h [(size_t)MR_*512];
__device__ h16 g_h2_h [(size_t)MR_*512];
__device__ h16 g_eT_h [(size_t)512*R_];
__device__ float g_part[(size_t)KSL*N_*512];
__device__ h16 g_up_h [(size_t)MN_*128];
__device__ h16 g_hn_h [(size_t)MN_*512];
__device__ h16 g_w1_h[512*64],  g_w1_l[512*64];
__device__ h16 g_w2_h[512*512];
__device__ h16 g_w3_h[64*512],  g_w3_l[64*512];
__device__ h16 g_w4_h[64*64],   g_w4_l[64*64];
__device__ h16 g_v1_h[512*128], g_v1_l[512*128];
__device__ h16 g_v2_h[32*512],  g_v2_l[32*512];

// ------------------------------- helpers ------------------------------------
__device__ __forceinline__ uint32_t smem_u32(const void* p){
    uint32_t a; asm("{ .reg .u64 t; cvta.to.shared.u64 t, %1; cvt.u32.u64 %0, t; }":"=r"(a):"l"(p)); return a;
}
__device__ __forceinline__ uint32_t swz(uint32_t off){ return off ^ ((off>>3)&0x70); }

__device__ __forceinline__ void cp16(uint32_t dst, const void* src){
    asm volatile("cp.async.cg.shared.global [%0], [%1], 16;" :: "r"(dst), "l"(src) : "memory");
}
__device__ __forceinline__ void cp_commit(){ asm volatile("cp.async.commit_group;" ::: "memory"); }
__device__ __forceinline__ void cp_wait(int k){
    if(k<=0)      asm volatile("cp.async.wait_group 0;" ::: "memory");
    else if(k==1) asm volatile("cp.async.wait_group 1;" ::: "memory");
    else          asm volatile("cp.async.wait_group 2;" ::: "memory");
}

__device__ __forceinline__ void ldm_x4(uint32_t* r,uint32_t a){
    asm volatile("ldmatrix.sync.aligned.m8n8.x4.shared.b16 {%0,%1,%2,%3},[%4];"
        :"=r"(r[0]),"=r"(r[1]),"=r"(r[2]),"=r"(r[3]):"r"(a));
}
__device__ __forceinline__ void ldm_x2(uint32_t* r,uint32_t a){
    asm volatile("ldmatrix.sync.aligned.m8n8.x2.shared.b16 {%0,%1},[%2];"
        :"=r"(r[0]),"=r"(r[1]):"r"(a));
}
__device__ __forceinline__ void mma_f16(float* d,const uint32_t* a,const uint32_t* b){
    asm volatile("mma.sync.aligned.m16n8k16.row.col.f32.f16.f16.f32 "
        "{%0,%1,%2,%3},{%4,%5,%6,%7},{%8,%9},{%0,%1,%2,%3};"
        : "+f"(d[0]),"+f"(d[1]),"+f"(d[2]),"+f"(d[3])
        : "r"(a[0]),"r"(a[1]),"r"(a[2]),"r"(a[3]),"r"(b[0]),"r"(b[1]));
}

// --------------------------- HMMA fp16 GEMM ---------------------------------
// D[M,N] = act(A[M,K] @ B[N,K]^T + bias).  A = fp16 hi plane.
// PASSES=2: B = hi+lo planes (2 MMA passes). PASSES=1: B = hi only.
// NBUF-deep cp.async ring over K chunks of 64.
// Buffer q at q*BUF: A @0 (16KB), B hi @16384 [, B lo @16384+BPL].
// MODE: 0 fp16 out (ldc); 1 fp32 out (ldc); 2 transposed edgeT out;
//       3 gather node out (ldc = col base 0/32).
template<int NT,int MODE,bool RELU,int PASSES,int NBUF>
__global__ __launch_bounds__(256)
void hm_gemm(const h16* __restrict__ Ah,int lda,
             const h16* __restrict__ Bh,const h16* __restrict__ Bl,int ldb,
             const float* __restrict__ bias,void* C0v,void* C1v,int ldc,
             size_t cZ,int stages,int kZ)
{
    extern __shared__ char smem[];
    const uint32_t sb = smem_u32(smem);
    const int tid=threadIdx.x, w=tid>>5, lane=tid&31;
    const int z=blockIdx.z, m0=blockIdx.y*128, n0=blockIdx.x*NT;
    const int kbase=z*kZ;
    constexpr int BPL = NT*128;                 // bytes per B plane
    constexpr uint32_t BUF = 16384u + (uint32_t)PASSES*BPL;
    constexpr int WARPS_M = (NT==128)?2:4;
    constexpr int WARPS_N = 8/WARPS_M;
    constexpr int WM = 128/WARPS_M;
    constexpr int WN = NT/WARPS_N;
    constexpr int MT = WM/16, NF = WN/8;
    const int wr = w % WARPS_M, wc = w / WARPS_M;

    float* Cf=nullptr; h16* Ch=nullptr; h16* Cl=nullptr;
    if(MODE==1) Cf=(float*)C0v + (size_t)z*cZ;
    else { Ch=(h16*)C0v; Cl=(h16*)C1v; }

    float acc[MT][NF][4];
#pragma unroll
    for(int i=0;i<MT;i++)
#pragma unroll
        for(int j=0;j<NF;j++)
#pragma unroll
            for(int q=0;q<4;q++) acc[i][j][q]=0.f;

    auto load_stage = [&](int s){
        const int kk = kbase + s*64;
        const uint32_t base = sb + (uint32_t)(s%NBUF)*BUF;
#pragma unroll
        for(int it=0;it<4;it++){
            int idx=tid+it*256, row=idx>>3, c=idx&7;
            cp16(base+swz((uint32_t)(row*128+c*16)),
                 Ah+(size_t)(m0+row)*lda+kk+c*8);
        }
#pragma unroll
        for(int pl=0;pl<PASSES;pl++){
            const h16* src = pl?Bl:Bh;
            const uint32_t dofs = base + 16384u + (uint32_t)pl*BPL;
#pragma unroll
            for(int it=0;it<NT/32;it++){
                int idx=tid+it*256, row=idx>>3, c=idx&7;
                cp16(dofs+swz((uint32_t)(row*128+c*16)),
                     src+(size_t)(n0+row)*ldb+kk+c*8);
            }
        }
        cp_commit();
    };

    // prologue: prefetch NBUF-1 stages
#pragma unroll
    for(int s0=0;s0<NBUF-1;s0++)
        if(s0<stages) load_stage(s0);

    for(int s=0;s<stages;s++){
        if(s+NBUF-1<stages) load_stage(s+NBUF-1);
        int k = stages - s - 1; if(k > NBUF-1) k = NBUF-1;
        cp_wait(k);
        __syncthreads();

        const uint32_t base = sb + (uint32_t)(s%NBUF)*BUF;
        const uint32_t bbase = base + 16384u;
#pragma unroll
        for(int k16=0;k16<4;k16++){
            uint32_t bh[NF][2], bl[NF][2];
#pragma unroll
            for(int nf=0;nf<NF;nf++){
                int row = wc*WN + nf*8 + (lane&7);
                int colb = k16*32 + ((lane>>3)&1)*16;
                uint32_t off = swz((uint32_t)(row*128+colb));
                ldm_x2(bh[nf], bbase + off);
                if(PASSES==2) ldm_x2(bl[nf], bbase + BPL + off);
            }
            uint32_t ar[MT][4];
#pragma unroll
            for(int mt=0;mt<MT;mt++){
                int row = wr*WM + mt*16 + (lane&15);
                int colb = k16*32 + (lane>>4)*16;
                ldm_x4(ar[mt], base + swz((uint32_t)(row*128+colb)));
            }
#pragma unroll
            for(int mt=0;mt<MT;mt++)
#pragma unroll
                for(int nf=0;nf<NF;nf++){
                    mma_f16(acc[mt][nf], ar[mt], bh[nf]);
                    if(PASSES==2) mma_f16(acc[mt][nf], ar[mt], bl[nf]);
                }
        }
        __syncthreads();
    }

    // ------------------------------- epilogue -------------------------------
    if(MODE==2){
        float* fbuf = reinterpret_cast<float*>(smem);
#pragma unroll
        for(int mt=0;mt<MT;mt++)
#pragma unroll
            for(int nf=0;nf<NF;nf++){
                int ln = wc*WN + nf*8 + 2*(lane&3);
                float b0=0.f,b1=0.f;
                if(bias){ b0=bias[n0+ln]; b1=bias[n0+ln+1]; }
#pragma unroll
                for(int rr=0;rr<2;rr++){
                    int lm = wr*WM + mt*16 + (lane>>2) + rr*8;
                    float v0=acc[mt][nf][rr*2+0]+b0;
                    float v1=acc[mt][nf][rr*2+1]+b1;
                    if(RELU){ v0=fmaxf(v0,0.f); v1=fmaxf(v1,0.f); }
                    fbuf[lm*(NT+1)+ln]=v0;
                    fbuf[lm*(NT+1)+ln+1]=v1;
                }
            }
        __syncthreads();
        const int bb = m0>>14, r0g = m0&(R_-1);
        for(int idx=tid; idx<NT*128; idx+=256){
            int nn=idx>>7, mm=idx&127;
            float v=fbuf[mm*(NT+1)+nn];
            size_t o=((size_t)bb*64+(n0+nn))*(size_t)R_ + r0g+mm;
            Ch[o]=__float2half_rn(v);
        }
        return;
    }

#pragma unroll
    for(int mt=0;mt<MT;mt++)
#pragma unroll
        for(int nf=0;nf<NF;nf++){
            int c0 = n0 + wc*WN + nf*8 + 2*(lane&3);
            float b0=0.f,b1=0.f;
            if(bias){ b0=bias[c0]; b1=bias[c0+1]; }
#pragma unroll
            for(int rr=0;rr<2;rr++){
                int gm = m0 + wr*WM + mt*16 + (lane>>2) + rr*8;
                float v0=acc[mt][nf][rr*2+0]+b0;
                float v1=acc[mt][nf][rr*2+1]+b1;
                if(RELU){ v0=fmaxf(v0,0.f); v1=fmaxf(v1,0.f); }
                if(MODE==1){
                    *reinterpret_cast<float2*>(Cf+(size_t)gm*ldc+c0)=make_float2(v0,v1);
                } else {
                    size_t o;
                    if(MODE==0) o=(size_t)gm*ldc+c0;
                    else        o=((size_t)(c0>>5)*R_+gm)*64 + ldc + (c0&31);
                    *reinterpret_cast<__half2*>(Ch+o)=__floats2half2_rn(v0,v1);
                }
            }
        }
}

// ------------------------------- prep kernels -------------------------------
__global__ void tsplit(const float* __restrict__ in,h16* __restrict__ oh,h16* __restrict__ ol,
                       h16* __restrict__ cpy,
                       int P,int ldin,int ldout,size_t inB,size_t outB)
{
    __shared__ float t[32][33];
    in+=(size_t)blockIdx.z*inB; oh+=(size_t)blockIdx.z*outB;
    if(ol) ol+=(size_t)blockIdx.z*outB;
    int p0=blockIdx.x*32, q0=blockIdx.y*32, tx=threadIdx.x, ty=threadIdx.y;
#pragma unroll
    for(int i=0;i<4;i++){
        int p=p0+ty+i*8; float v=0.f;
        if(p<P){
            v=in[(size_t)p*ldin+q0+tx];
            if(cpy) cpy[(size_t)p*ldin+q0+tx]=__float2half_rn(v);
        }
        t[ty+i*8][tx]=v;
    }
    __syncthreads();
#pragma unroll
    for(int i=0;i<4;i++){
        int q=q0+ty+i*8, pp=p0+tx;
        float v=t[tx][ty+i*8];
        h16 hi=__float2half_rn(v);
        oh[(size_t)q*ldout+pp]=hi;
        if(ol) ol[(size_t)q*ldout+pp]=__float2half_rn(v-__half2float(hi));
    }
}
__global__ void reduce_concat(const float* __restrict__ obj,const float* __restrict__ part,
                              h16* __restrict__ uh)
{
    int i=blockIdx.x*256+threadIdx.x; if(i>=MN_*128) return;
    int col=i&127, bn=i>>7;
    float v=0.f;
    if(col<32) v=obj[(size_t)bn*32+col];
    else if(col<96){
        int e=col-32, b=bn>>10, n=bn&1023;
        size_t base=(size_t)n*512+b*64+e;
#pragma unroll
        for(int ks=0;ks<KSL;ks++) v+=part[(size_t)ks*N_*512+base];
    }
    uh[i]=__float2half_rn(v);
}

// ---------------------------------- host ------------------------------------
static inline int smB(int nt,int passes,int nbuf){
    int b = nbuf*(16384 + passes*nt*128);
    int epi = 128*(nt+1)*4;           // MODE2 staging floor
    return b > epi ? b : epi;
}

extern "C" void kernel_launch(void* const* d_in,const int* in_sizes,int n_in,
                              void* d_out,int out_size)
{
    const float* obj=(const float*)d_in[0];
    const float* Rs =(const float*)d_in[1];
    const float* Rr =(const float*)d_in[2];
    const float* rw1=(const float*)d_in[3];  const float* rb1=(const float*)d_in[4];
    const float* rw2=(const float*)d_in[5];  const float* rb2=(const float*)d_in[6];
    const float* rw3=(const float*)d_in[7];  const float* rb3=(const float*)d_in[8];
    const float* rw4=(const float*)d_in[9];  const float* rb4=(const float*)d_in[10];
    const float* ow1=(const float*)d_in[11]; const float* ob1=(const float*)d_in[12];
    const float* ow2=(const float*)d_in[13]; const float* ob2=(const float*)d_in[14];
    float* out=(float*)d_out;

    h16 *RsTh,*RrTh,*Rrh,*oTh,*ndh,*h1h,*h2h,*eTh,*uph,*hnh;
    h16 *w1h,*w1l,*w2h,*w3h,*w3l,*w4h,*w4l,*v1h,*v1l,*v2h,*v2l;
    float* part;
    cudaGetSymbolAddress((void**)&RsTh,g_RsT_h);
    cudaGetSymbolAddress((void**)&RrTh,g_RrT_h);
    cudaGetSymbolAddress((void**)&Rrh,g_Rr_h);
    cudaGetSymbolAddress((void**)&oTh,g_oT_h);
    cudaGetSymbolAddress((void**)&ndh,g_nd_h);
    cudaGetSymbolAddress((void**)&h1h,g_h1_h);
    cudaGetSymbolAddress((void**)&h2h,g_h2_h);
    cudaGetSymbolAddress((void**)&eTh,g_eT_h);
    cudaGetSymbolAddress((void**)&part,g_part);
    cudaGetSymbolAddress((void**)&uph,g_up_h);
    cudaGetSymbolAddress((void**)&hnh,g_hn_h);
    cudaGetSymbolAddress((void**)&w1h,g_w1_h);   cudaGetSymbolAddress((void**)&w1l,g_w1_l);
    cudaGetSymbolAddress((void**)&w2h,g_w2_h);
    cudaGetSymbolAddress((void**)&w3h,g_w3_h);   cudaGetSymbolAddress((void**)&w3l,g_w3_l);
    cudaGetSymbolAddress((void**)&w4h,g_w4_h);   cudaGetSymbolAddress((void**)&w4l,g_w4_l);
    cudaGetSymbolAddress((void**)&v1h,g_v1_h);   cudaGetSymbolAddress((void**)&v1l,g_v1_l);
    cudaGetSymbolAddress((void**)&v2h,g_v2_h);   cudaGetSymbolAddress((void**)&v2l,g_v2_l);

    cudaFuncSetAttribute(hm_gemm<128,3,false,1,3>,cudaFuncAttributeMaxDynamicSharedMemorySize,smB(128,1,3));
    cudaFuncSetAttribute(hm_gemm<128,0,true ,2,1>,cudaFuncAttributeMaxDynamicSharedMemorySize,smB(128,2,1));
    cudaFuncSetAttribute(hm_gemm<128,0,true ,1,3>,cudaFuncAttributeMaxDynamicSharedMemorySize,smB(128,1,3));
    cudaFuncSetAttribute(hm_gemm< 64,0,true ,2,3>,cudaFuncAttributeMaxDynamicSharedMemorySize,smB(64,2,3));
    cudaFuncSetAttribute(hm_gemm< 64,2,true ,2,2>,cudaFuncAttributeMaxDynamicSharedMemorySize,smB(64,2,2));
    cudaFuncSetAttribute(hm_gemm<128,1,false,1,3>,cudaFuncAttributeMaxDynamicSharedMemorySize,smB(128,1,3));
    cudaFuncSetAttribute(hm_gemm<128,0,true ,2,2>,cudaFuncAttributeMaxDynamicSharedMemorySize,smB(128,2,2));
    cudaFuncSetAttribute(hm_gemm< 32,1,false,2,3>,cudaFuncAttributeMaxDynamicSharedMemorySize,smB(32,2,3));

    dim3 tb(32,8);
    // prep: transposes + splits
    tsplit<<<dim3(32,512,1),tb>>>(Rs, RsTh,nullptr,nullptr, 1024,R_,1024, 0,0);
    tsplit<<<dim3(32,512,1),tb>>>(Rr, RrTh,nullptr,Rrh, 1024,R_,1024, 0,0);
    tsplit<<<dim3(32,1,8),tb>>>(obj, oTh,nullptr,nullptr, 1024,32,1024, (size_t)N_*32,(size_t)32*N_);
    tsplit<<<dim3(2,16,1),tb>>>(rw1, w1h,w1l,nullptr, 64,512,64, 0,0);
    tsplit<<<dim3(16,16,1),tb>>>(rw2, w2h,nullptr,nullptr, 512,512,512, 0,0);
    tsplit<<<dim3(16,2,1),tb>>>(rw3, w3h,w3l,nullptr, 512,64,512, 0,0);
    tsplit<<<dim3(2,2,1),tb>>>(rw4, w4h,w4l,nullptr, 64,64,64, 0,0);
    tsplit<<<dim3(4,16,1),tb>>>(ow1, v1h,v1l,nullptr, 96,512,128, 0,0);
    tsplit<<<dim3(16,1,1),tb>>>(ow2, v2h,v2l,nullptr, 512,32,512, 0,0);

    // gather: node[b*R+r, 0:32]=src(Rs), [32:64]=dst(Rr)   (1-pass, 3-deep)
    hm_gemm<128,3,false,1,3><<<dim3(2,128,1),256,smB(128,1,3)>>>(RsTh,1024, oTh,nullptr,1024, nullptr, ndh,nullptr, 0, 0, 16,0);
    hm_gemm<128,3,false,1,3><<<dim3(2,128,1),256,smB(128,1,3)>>>(RrTh,1024, oTh,nullptr,1024, nullptr, ndh,nullptr, 32,0, 16,0);
    // edge MLP
    hm_gemm<128,0,true ,2,1><<<dim3(4,1024,1),256,smB(128,2,1)>>>(ndh,64,  w1h,w1l,64,  rb1, h1h,nullptr, 512,0, 1,0);
    hm_gemm<128,0,true ,1,3><<<dim3(4,1024,1),256,smB(128,1,3)>>>(h1h,512, w2h,nullptr,512, rb2, h2h,nullptr, 512,0, 8,0);
    hm_gemm< 64,0,true ,2,3><<<dim3(1,1024,1),256,smB(64,2,3)>>>(h2h,512, w3h,w3l,512, rb3, ndh,nullptr, 64,0, 8,0);
    hm_gemm< 64,2,true ,2,2><<<dim3(1,1024,1),256,smB(64,2,2)>>>(ndh,64,  w4h,w4l,64,  rb4, eTh,nullptr, 0,0, 1,0);
    // scatter-aggregate (1-pass, 3-deep, split-K=16), then reduce+concat
    hm_gemm<128,1,false,1,3><<<dim3(4,8,KSL),256,smB(128,1,3)>>>(Rrh,R_, eTh,nullptr,R_, nullptr, part,nullptr, 512,(size_t)N_*512, 16,1024);
    reduce_concat<<<(MN_*128+255)/256,256>>>(obj, part, uph);
    // node MLP (2-pass)
    hm_gemm<128,0,true ,2,2><<<dim3(4,64,1),256,smB(128,2,2)>>>(uph,128, v1h,v1l,128, ob1, hnh,nullptr, 512,0, 2,0);
    hm_gemm< 32,1,false,2,3><<<dim3(1,64,1),256,smB(32,2,3)>>>(hnh,512, v2h,v2l,512, ob2, out,nullptr, 32,0, 8,0);
}

// round 16
// speedup vs baseline: 1.8293x; 1.1078x over previous
#include <cuda_runtime.h>
#include <cuda_fp16.h>
#include <cstdint>
#include <cstddef>

#define B_  8
#define N_  1024
#define R_  16384
#define MR_ (B_*R_)
#define MN_ (B_*N_)
#define KSL 16

typedef __half h16;

// ------------------------- scratch (device globals) -------------------------
__device__ h16 g_RsT_h[(size_t)R_*N_];
__device__ h16 g_RrT_h[(size_t)R_*N_];
__device__ h16 g_Rr_h [(size_t)N_*R_];
__device__ h16 g_oT_h [(size_t)256*N_];
__device__ h16 g_nd_h [(size_t)MR_*64];
__device__ h16 g_h1_h [(size_t)MR_*512];
__device__ h16 g_h2_h [(size_t)MR_*512];
__device__ h16 g_eT_h [(size_t)512*R_];
__device__ float g_part[(size_t)KSL*N_*512];
__device__ h16 g_up_h [(size_t)MN_*128];
__device__ h16 g_hn_h [(size_t)MN_*512];
__device__ h16 g_w1_h[512*64];
__device__ h16 g_w2_h[512*512];
__device__ h16 g_w3_h[64*512];
__device__ h16 g_w4_h[64*64];
__device__ h16 g_v1_h[512*128], g_v1_l[512*128];
__device__ h16 g_v2_h[32*512],  g_v2_l[32*512];

// ------------------------------- helpers ------------------------------------
__device__ __forceinline__ uint32_t smem_u32(const void* p){
    uint32_t a; asm("{ .reg .u64 t; cvta.to.shared.u64 t, %1; cvt.u32.u64 %0, t; }":"=r"(a):"l"(p)); return a;
}
__device__ __forceinline__ uint32_t swz(uint32_t off){ return off ^ ((off>>3)&0x70); }

__device__ __forceinline__ void cp16(uint32_t dst, const void* src){
    asm volatile("cp.async.cg.shared.global [%0], [%1], 16;" :: "r"(dst), "l"(src) : "memory");
}
__device__ __forceinline__ void cp_commit(){ asm volatile("cp.async.commit_group;" ::: "memory"); }
__device__ __forceinline__ void cp_wait(int k){
    if(k<=0)      asm volatile("cp.async.wait_group 0;" ::: "memory");
    else if(k==1) asm volatile("cp.async.wait_group 1;" ::: "memory");
    else          asm volatile("cp.async.wait_group 2;" ::: "memory");
}

__device__ __forceinline__ void ldm_x4(uint32_t* r,uint32_t a){
    asm volatile("ldmatrix.sync.aligned.m8n8.x4.shared.b16 {%0,%1,%2,%3},[%4];"
        :"=r"(r[0]),"=r"(r[1]),"=r"(r[2]),"=r"(r[3]):"r"(a));
}
__device__ __forceinline__ void ldm_x2(uint32_t* r,uint32_t a){
    asm volatile("ldmatrix.sync.aligned.m8n8.x2.shared.b16 {%0,%1},[%2];"
        :"=r"(r[0]),"=r"(r[1]):"r"(a));
}
__device__ __forceinline__ void mma_f16(float* d,const uint32_t* a,const uint32_t* b){
    asm volatile("mma.sync.aligned.m16n8k16.row.col.f32.f16.f16.f32 "
        "{%0,%1,%2,%3},{%4,%5,%6,%7},{%8,%9},{%0,%1,%2,%3};"
        : "+f"(d[0]),"+f"(d[1]),"+f"(d[2]),"+f"(d[3])
        : "r"(a[0]),"r"(a[1]),"r"(a[2]),"r"(a[3]),"r"(b[0]),"r"(b[1]));
}

// --------------------------- HMMA fp16 GEMM ---------------------------------
// D[M,N] = act(A[M,K] @ B[N,K]^T + bias).  A = fp16 hi plane.
// PASSES=2: B = hi+lo planes (2 MMA passes). PASSES=1: B = hi only.
// NBUF-deep cp.async ring over K chunks of 64.
// Buffer q at q*BUF: A @0 (16KB), B hi @16384 [, B lo @16384+BPL].
// MODE: 0 fp16 out (ldc); 1 fp32 out (ldc); 2 transposed edgeT out;
//       3 merged gather: z selects A (Ah vs Ah2) and col base z*32.
template<int NT,int MODE,bool RELU,int PASSES,int NBUF>
__global__ __launch_bounds__(256)
void hm_gemm(const h16* __restrict__ Ah,const h16* __restrict__ Ah2,int lda,
             const h16* __restrict__ Bh,const h16* __restrict__ Bl,int ldb,
             const float* __restrict__ bias,void* C0v,void* C1v,int ldc,
             size_t cZ,int stages,int kZ)
{
    extern __shared__ char smem[];
    const uint32_t sb = smem_u32(smem);
    const int tid=threadIdx.x, w=tid>>5, lane=tid&31;
    const int z=blockIdx.z, m0=blockIdx.y*128, n0=blockIdx.x*NT;
    const int kbase = (MODE==3) ? 0 : z*kZ;
    const h16* Asel = (MODE==3 && z==1) ? Ah2 : Ah;
    const int zbase = (MODE==3) ? z*32 : ldc;
    constexpr int BPL = NT*128;                 // bytes per B plane
    constexpr uint32_t BUF = 16384u + (uint32_t)PASSES*BPL;
    constexpr int WARPS_M = (NT==128)?2:4;
    constexpr int WARPS_N = 8/WARPS_M;
    constexpr int WM = 128/WARPS_M;
    constexpr int WN = NT/WARPS_N;
    constexpr int MT = WM/16, NF = WN/8;
    const int wr = w % WARPS_M, wc = w / WARPS_M;

    float* Cf=nullptr; h16* Ch=nullptr; h16* Cl=nullptr;
    if(MODE==1) Cf=(float*)C0v + (size_t)z*cZ;
    else { Ch=(h16*)C0v; Cl=(h16*)C1v; }

    float acc[MT][NF][4];
#pragma unroll
    for(int i=0;i<MT;i++)
#pragma unroll
        for(int j=0;j<NF;j++)
#pragma unroll
            for(int q=0;q<4;q++) acc[i][j][q]=0.f;

    auto load_stage = [&](int s){
        const int kk = kbase + s*64;
        const uint32_t base = sb + (uint32_t)(s%NBUF)*BUF;
#pragma unroll
        for(int it=0;it<4;it++){
            int idx=tid+it*256, row=idx>>3, c=idx&7;
            cp16(base+swz((uint32_t)(row*128+c*16)),
                 Asel+(size_t)(m0+row)*lda+kk+c*8);
        }
#pragma unroll
        for(int pl=0;pl<PASSES;pl++){
            const h16* src = pl?Bl:Bh;
            const uint32_t dofs = base + 16384u + (uint32_t)pl*BPL;
#pragma unroll
            for(int it=0;it<NT/32;it++){
                int idx=tid+it*256, row=idx>>3, c=idx&7;
                cp16(dofs+swz((uint32_t)(row*128+c*16)),
                     src+(size_t)(n0+row)*ldb+kk+c*8);
            }
        }
        cp_commit();
    };

    // prologue: prefetch NBUF-1 stages
#pragma unroll
    for(int s0=0;s0<NBUF-1;s0++)
        if(s0<stages) load_stage(s0);

    for(int s=0;s<stages;s++){
        if(s+NBUF-1<stages) load_stage(s+NBUF-1);
        int k = stages - s - 1; if(k > NBUF-1) k = NBUF-1;
        cp_wait(k);
        __syncthreads();

        const uint32_t base = sb + (uint32_t)(s%NBUF)*BUF;
        const uint32_t bbase = base + 16384u;
#pragma unroll
        for(int k16=0;k16<4;k16++){
            uint32_t bh[NF][2], bl[NF][2];
#pragma unroll
            for(int nf=0;nf<NF;nf++){
                int row = wc*WN + nf*8 + (lane&7);
                int colb = k16*32 + ((lane>>3)&1)*16;
                uint32_t off = swz((uint32_t)(row*128+colb));
                ldm_x2(bh[nf], bbase + off);
                if(PASSES==2) ldm_x2(bl[nf], bbase + BPL + off);
            }
            uint32_t ar[MT][4];
#pragma unroll
            for(int mt=0;mt<MT;mt++){
                int row = wr*WM + mt*16 + (lane&15);
                int colb = k16*32 + (lane>>4)*16;
                ldm_x4(ar[mt], base + swz((uint32_t)(row*128+colb)));
            }
#pragma unroll
            for(int mt=0;mt<MT;mt++)
#pragma unroll
                for(int nf=0;nf<NF;nf++){
                    mma_f16(acc[mt][nf], ar[mt], bh[nf]);
                    if(PASSES==2) mma_f16(acc[mt][nf], ar[mt], bl[nf]);
                }
        }
        __syncthreads();
    }

    // ------------------------------- epilogue -------------------------------
    if(MODE==2){
        float* fbuf = reinterpret_cast<float*>(smem);
#pragma unroll
        for(int mt=0;mt<MT;mt++)
#pragma unroll
            for(int nf=0;nf<NF;nf++){
                int ln = wc*WN + nf*8 + 2*(lane&3);
                float b0=0.f,b1=0.f;
                if(bias){ b0=bias[n0+ln]; b1=bias[n0+ln+1]; }
#pragma unroll
                for(int rr=0;rr<2;rr++){
                    int lm = wr*WM + mt*16 + (lane>>2) + rr*8;
                    float v0=acc[mt][nf][rr*2+0]+b0;
                    float v1=acc[mt][nf][rr*2+1]+b1;
                    if(RELU){ v0=fmaxf(v0,0.f); v1=fmaxf(v1,0.f); }
                    fbuf[lm*(NT+1)+ln]=v0;
                    fbuf[lm*(NT+1)+ln+1]=v1;
                }
            }
        __syncthreads();
        const int bb = m0>>14, r0g = m0&(R_-1);
        for(int idx=tid; idx<NT*128; idx+=256){
            int nn=idx>>7, mm=idx&127;
            float v=fbuf[mm*(NT+1)+nn];
            size_t o=((size_t)bb*64+(n0+nn))*(size_t)R_ + r0g+mm;
            Ch[o]=__float2half_rn(v);
        }
        return;
    }

#pragma unroll
    for(int mt=0;mt<MT;mt++)
#pragma unroll
        for(int nf=0;nf<NF;nf++){
            int c0 = n0 + wc*WN + nf*8 + 2*(lane&3);
            float b0=0.f,b1=0.f;
            if(bias){ b0=bias[c0]; b1=bias[c0+1]; }
#pragma unroll
            for(int rr=0;rr<2;rr++){
                int gm = m0 + wr*WM + mt*16 + (lane>>2) + rr*8;
                float v0=acc[mt][nf][rr*2+0]+b0;
                float v1=acc[mt][nf][rr*2+1]+b1;
                if(RELU){ v0=fmaxf(v0,0.f); v1=fmaxf(v1,0.f); }
                if(MODE==1){
                    *reinterpret_cast<float2*>(Cf+(size_t)gm*ldc+c0)=make_float2(v0,v1);
                } else {
                    size_t o;
                    if(MODE==0) o=(size_t)gm*ldc+c0;
                    else        o=((size_t)(c0>>5)*R_+gm)*64 + zbase + (c0&31);
                    *reinterpret_cast<__half2*>(Ch+o)=__floats2half2_rn(v0,v1);
                }
            }
        }
}

// ------------------------------- prep kernels -------------------------------
__global__ void tsplit(const float* __restrict__ in,h16* __restrict__ oh,h16* __restrict__ ol,
                       h16* __restrict__ cpy,
                       int P,int ldin,int ldout,size_t inB,size_t outB)
{
    __shared__ float t[32][33];
    in+=(size_t)blockIdx.z*inB; oh+=(size_t)blockIdx.z*outB;
    if(ol) ol+=(size_t)blockIdx.z*outB;
    int p0=blockIdx.x*32, q0=blockIdx.y*32, tx=threadIdx.x, ty=threadIdx.y;
#pragma unroll
    for(int i=0;i<4;i++){
        int p=p0+ty+i*8; float v=0.f;
        if(p<P){
            v=in[(size_t)p*ldin+q0+tx];
            if(cpy) cpy[(size_t)p*ldin+q0+tx]=__float2half_rn(v);
        }
        t[ty+i*8][tx]=v;
    }
    __syncthreads();
#pragma unroll
    for(int i=0;i<4;i++){
        int q=q0+ty+i*8, pp=p0+tx;
        float v=t[tx][ty+i*8];
        h16 hi=__float2half_rn(v);
        oh[(size_t)q*ldout+pp]=hi;
        if(ol) ol[(size_t)q*ldout+pp]=__float2half_rn(v-__half2float(hi));
    }
}
__global__ void reduce_concat(const float* __restrict__ obj,const float* __restrict__ part,
                              h16* __restrict__ uh)
{
    int i=blockIdx.x*256+threadIdx.x; if(i>=MN_*128) return;
    int col=i&127, bn=i>>7;
    float v=0.f;
    if(col<32) v=obj[(size_t)bn*32+col];
    else if(col<96){
        int e=col-32, b=bn>>10, n=bn&1023;
        size_t base=(size_t)n*512+b*64+e;
#pragma unroll
        for(int ks=0;ks<KSL;ks++) v+=part[(size_t)ks*N_*512+base];
    }
    uh[i]=__float2half_rn(v);
}

// ---------------------------------- host ------------------------------------
static inline int smB(int nt,int passes,int nbuf){
    int b = nbuf*(16384 + passes*nt*128);
    int epi = 128*(nt+1)*4;           // MODE2 staging floor
    return b > epi ? b : epi;
}

extern "C" void kernel_launch(void* const* d_in,const int* in_sizes,int n_in,
                              void* d_out,int out_size)
{
    const float* obj=(const float*)d_in[0];
    const float* Rs =(const float*)d_in[1];
    const float* Rr =(const float*)d_in[2];
    const float* rw1=(const float*)d_in[3];  const float* rb1=(const float*)d_in[4];
    const float* rw2=(const float*)d_in[5];  const float* rb2=(const float*)d_in[6];
    const float* rw3=(const float*)d_in[7];  const float* rb3=(const float*)d_in[8];
    const float* rw4=(const float*)d_in[9];  const float* rb4=(const float*)d_in[10];
    const float* ow1=(const float*)d_in[11]; const float* ob1=(const float*)d_in[12];
    const float* ow2=(const float*)d_in[13]; const float* ob2=(const float*)d_in[14];
    float* out=(float*)d_out;

    h16 *RsTh,*RrTh,*Rrh,*oTh,*ndh,*h1h,*h2h,*eTh,*uph,*hnh;
    h16 *w1h,*w2h,*w3h,*w4h,*v1h,*v1l,*v2h,*v2l;
    float* part;
    cudaGetSymbolAddress((void**)&RsTh,g_RsT_h);
    cudaGetSymbolAddress((void**)&RrTh,g_RrT_h);
    cudaGetSymbolAddress((void**)&Rrh,g_Rr_h);
    cudaGetSymbolAddress((void**)&oTh,g_oT_h);
    cudaGetSymbolAddress((void**)&ndh,g_nd_h);
    cudaGetSymbolAddress((void**)&h1h,g_h1_h);
    cudaGetSymbolAddress((void**)&h2h,g_h2_h);
    cudaGetSymbolAddress((void**)&eTh,g_eT_h);
    cudaGetSymbolAddress((void**)&part,g_part);
    cudaGetSymbolAddress((void**)&uph,g_up_h);
    cudaGetSymbolAddress((void**)&hnh,g_hn_h);
    cudaGetSymbolAddress((void**)&w1h,g_w1_h);
    cudaGetSymbolAddress((void**)&w2h,g_w2_h);
    cudaGetSymbolAddress((void**)&w3h,g_w3_h);
    cudaGetSymbolAddress((void**)&w4h,g_w4_h);
    cudaGetSymbolAddress((void**)&v1h,g_v1_h);   cudaGetSymbolAddress((void**)&v1l,g_v1_l);
    cudaGetSymbolAddress((void**)&v2h,g_v2_h);   cudaGetSymbolAddress((void**)&v2l,g_v2_l);

    cudaFuncSetAttribute(hm_gemm<128,3,false,1,3>,cudaFuncAttributeMaxDynamicSharedMemorySize,smB(128,1,3));
    cudaFuncSetAttribute(hm_gemm<128,0,true ,1,1>,cudaFuncAttributeMaxDynamicSharedMemorySize,smB(128,1,1));
    cudaFuncSetAttribute(hm_gemm<128,0,true ,1,3>,cudaFuncAttributeMaxDynamicSharedMemorySize,smB(128,1,3));
    cudaFuncSetAttribute(hm_gemm< 64,0,true ,1,3>,cudaFuncAttributeMaxDynamicSharedMemorySize,smB(64,1,3));
    cudaFuncSetAttribute(hm_gemm< 64,2,true ,1,2>,cudaFuncAttributeMaxDynamicSharedMemorySize,smB(64,1,2));
    cudaFuncSetAttribute(hm_gemm<128,1,false,1,3>,cudaFuncAttributeMaxDynamicSharedMemorySize,smB(128,1,3));
    cudaFuncSetAttribute(hm_gemm<128,0,true ,2,2>,cudaFuncAttributeMaxDynamicSharedMemorySize,smB(128,2,2));
    cudaFuncSetAttribute(hm_gemm< 32,1,false,2,3>,cudaFuncAttributeMaxDynamicSharedMemorySize,smB(32,2,3));

    dim3 tb(32,8);
    // prep: transposes + splits (lo planes only for node-MLP weights)
    tsplit<<<dim3(32,512,1),tb>>>(Rs, RsTh,nullptr,nullptr, 1024,R_,1024, 0,0);
    tsplit<<<dim3(32,512,1),tb>>>(Rr, RrTh,nullptr,Rrh, 1024,R_,1024, 0,0);
    tsplit<<<dim3(32,1,8),tb>>>(obj, oTh,nullptr,nullptr, 1024,32,1024, (size_t)N_*32,(size_t)32*N_);
    tsplit<<<dim3(2,16,1),tb>>>(rw1, w1h,nullptr,nullptr, 64,512,64, 0,0);
    tsplit<<<dim3(16,16,1),tb>>>(rw2, w2h,nullptr,nullptr, 512,512,512, 0,0);
    tsplit<<<dim3(16,2,1),tb>>>(rw3, w3h,nullptr,nullptr, 512,64,512, 0,0);
    tsplit<<<dim3(2,2,1),tb>>>(rw4, w4h,nullptr,nullptr, 64,64,64, 0,0);
    tsplit<<<dim3(4,16,1),tb>>>(ow1, v1h,v1l,nullptr, 96,512,128, 0,0);
    tsplit<<<dim3(16,1,1),tb>>>(ow2, v2h,v2l,nullptr, 512,32,512, 0,0);

    // merged gather: z=0 -> node[:,0:32]=Rs-src, z=1 -> node[:,32:64]=Rr-dst
    hm_gemm<128,3,false,1,3><<<dim3(2,128,2),256,smB(128,1,3)>>>(RsTh,RrTh,1024, oTh,nullptr,1024, nullptr, ndh,nullptr, 0, 0, 16,0);
    // edge MLP (all 1-pass)
    hm_gemm<128,0,true ,1,1><<<dim3(4,1024,1),256,smB(128,1,1)>>>(ndh,nullptr,64,  w1h,nullptr,64,  rb1, h1h,nullptr, 512,0, 1,0);
    hm_gemm<128,0,true ,1,3><<<dim3(4,1024,1),256,smB(128,1,3)>>>(h1h,nullptr,512, w2h,nullptr,512, rb2, h2h,nullptr, 512,0, 8,0);
    hm_gemm< 64,0,true ,1,3><<<dim3(1,1024,1),256,smB(64,1,3)>>>(h2h,nullptr,512, w3h,nullptr,512, rb3, ndh,nullptr, 64,0, 8,0);
    hm_gemm< 64,2,true ,1,2><<<dim3(1,1024,1),256,smB(64,1,2)>>>(ndh,nullptr,64,  w4h,nullptr,64,  rb4, eTh,nullptr, 0,0, 1,0);
    // scatter-aggregate (1-pass, 3-deep, split-K=16), then reduce+concat
    hm_gemm<128,1,false,1,3><<<dim3(4,8,KSL),256,smB(128,1,3)>>>(Rrh,nullptr,R_, eTh,nullptr,R_, nullptr, part,nullptr, 512,(size_t)N_*512, 16,1024);
    reduce_concat<<<(MN_*128+255)/256,256>>>(obj, part, uph);
    // node MLP (2-pass hedge)
    hm_gemm<128,0,true ,2,2><<<dim3(4,64,1),256,smB(128,2,2)>>>(uph,nullptr,128, v1h,v1l,128, ob1, hnh,nullptr, 512,0, 2,0);
    hm_gemm< 32,1,false,2,3><<<dim3(1,64,1),256,smB(32,2,3)>>>(hnh,nullptr,512, v2h,v2l,512, ob2, out,nullptr, 32,0, 8,0);
}